// round 1
// baseline (speedup 1.0000x reference)
#include <cuda_runtime.h>
#include <cstdint>

// ---------------------------------------------------------------------------
// FuseBlock: B=2, C=128, H=W=256.  Layout (b, c, h, w), HW = 65536.
// Pipeline:
//  stats1(x) -> m1,r1
//  fold(w_h1,norm1) -> W1',s1,t1 ; fold(w_h2,norm3,b_h2) -> W2',s2,t2
//  K1  GEMM: hidden = r1*(W1'@x - m1*s1) + t1                 -> bufA (768ch)
//  K2  dwconv3(hidden, w_dw1)                                  -> bufB (qkv)
//  K3a attn = circconv8x8(q,k) per patch/channel               -> bufA[0:]
//  stats2(attn,256) -> m2,r2
//  K3b GEMM: x1 = x + scale1 * ( w_p1 @ ( v * LN2(attn) ) )    -> bufA+OFF_X1
//  stats3(x1) -> m3,r3
//  K4  GEMM: h = r3*(W2'@x1 - m3*s2) + t2                      -> bufB (256ch)
//  K5a g = dw3(h)[0:128] * dw3(h)[128:256]                     -> bufB+OFF_G
//  K5b GEMM: out = x1 + scale2 * (w_p2 @ g)                    -> d_out
// ---------------------------------------------------------------------------

#define HWSZ   65536
#define NPIX   131072
#define EPSV   1e-6f

// scratch (device globals; allocation-free contract)
__device__ float g_bufA[100663296];   // 2*768*65536
__device__ float g_bufB[100663296];
__device__ float g_misc[2097152];

// offsets (floats) in g_misc
#define OFF_M1   0
#define OFF_R1   131072
#define OFF_M2   262144
#define OFF_R2   393216
#define OFF_M3   524288
#define OFF_R3   655360
#define OFF_W1P  786432     // 768*128
#define OFF_S1   884736
#define OFF_T1   885504
#define OFF_W2P  886272     // 256*128
#define OFF_S2   919040
#define OFF_T2   919296

#define OFF_X1   50331648   // x1 inside bufA (attn uses [0, 33554432))
#define OFF_G    50331648   // g  inside bufB (h    uses [0, 33554432))

// ---------------------------------------------------------------------------
// per-pixel channel mean / rstd   (LayerNorm stats, biased variance)
// ---------------------------------------------------------------------------
__global__ void stats_kernel(const float* __restrict__ in, float* __restrict__ mean,
                             float* __restrict__ rstd, int C) {
    int p = blockIdx.x * blockDim.x + threadIdx.x;     // 0..NPIX-1
    int b = p >> 16, hw = p & 65535;
    const float* base = in + ((size_t)(b * C) << 16) + hw;
    float s = 0.f, ss = 0.f;
    for (int c = 0; c < C; c += 4) {
        float v0 = base[(size_t)(c + 0) << 16];
        float v1 = base[(size_t)(c + 1) << 16];
        float v2 = base[(size_t)(c + 2) << 16];
        float v3 = base[(size_t)(c + 3) << 16];
        s  += v0 + v1 + v2 + v3;
        ss += v0 * v0 + v1 * v1 + v2 * v2 + v3 * v3;
    }
    float invC = 1.f / (float)C;
    float m = s * invC;
    float var = ss * invC - m * m;
    mean[p] = m;
    rstd[p] = rsqrtf(var + EPSV);
}

// ---------------------------------------------------------------------------
// fold LN weight into conv weight:  W'[o,c] = W[o,c]*nw[c]
//   s[o] = sum_c W'[o,c] ;  t[o] = sum_c W[o,c]*nb[c] (+ bias[o])
// ---------------------------------------------------------------------------
__global__ void fold_kernel(const float* __restrict__ wmat, const float* __restrict__ nw,
                            const float* __restrict__ nb, const float* __restrict__ bias,
                            float* __restrict__ wp, float* __restrict__ srow,
                            float* __restrict__ trow, int M, int K) {
    int o = blockIdx.x * blockDim.x + threadIdx.x;
    if (o >= M) return;
    float s = 0.f, t = 0.f;
    for (int c = 0; c < K; c++) {
        float wv  = wmat[o * K + c];
        float wpv = wv * nw[c];
        wp[o * K + c] = wpv;
        s += wpv;
        t += wv * nb[c];
    }
    if (bias) t += bias[o];
    srow[o] = s;
    trow[o] = t;
}

// ---------------------------------------------------------------------------
// SGEMM  C[M, NPIX] = A[M,K] @ B[K, NPIX]  with per-mode prologue/epilogue.
// B/C layouts: elem(k,n): b = n>>16, ((b*CB + k) << 16) + (n & 65535)
// MODE 1: out = colRstd[n]*(acc - colMean[n]*rowS[o]) + rowT[o]
// MODE 2: out = Xres[o,n] + acc*scaleRow[o]
// MODE 3: like 2, but B element = v[c,n] * ((attn[c,n]-m2[n])*r2[n]*lnW[c] + lnB[c])
//         (attn ptr = B with 256 ch; v lives in qkv buffer at ch 512+c of 768)
// Tiles: BM=BN=128, BK=8, 256 threads, 8x8 per thread, double-buffered smem.
// ---------------------------------------------------------------------------
template <int MODE>
__global__ __launch_bounds__(256)
void gemm_kernel(const float* __restrict__ A, const float* __restrict__ B,
                 float* __restrict__ Cc, int M, int K, int CB, int CO,
                 const float* __restrict__ colMean, const float* __restrict__ colRstd,
                 const float* __restrict__ rowS, const float* __restrict__ rowT,
                 const float* __restrict__ vbuf, const float* __restrict__ lnW,
                 const float* __restrict__ lnB, const float* __restrict__ Xres,
                 const float* __restrict__ scaleRow)
{
    __shared__ float As[2][8][128];
    __shared__ float Bs[2][8][128];

    const int t   = threadIdx.x;
    const int n0  = blockIdx.x * 128;
    const int m0  = blockIdx.y * 128;
    const int bg  = n0 >> 16;
    const int hw0 = n0 & 65535;

    const int aRow = t >> 1, aCol = (t & 1) * 4;
    const int bRow = t >> 5, bCol = (t & 31) * 4;

    const float* Aptr = A + (size_t)(m0 + aRow) * K + aCol;

    auto loadA = [&](int kt) -> float4 {
        return *reinterpret_cast<const float4*>(Aptr + kt * 8);
    };
    auto loadB = [&](int kt) -> float4 {
        int kg = kt * 8 + bRow;
        if (MODE == 3) {
            const float* ap = B    + (((size_t)(bg * 256 + kg))       << 16) + hw0 + bCol;
            const float* vp = vbuf + (((size_t)(bg * 768 + 512 + kg)) << 16) + hw0 + bCol;
            float4 a4 = *reinterpret_cast<const float4*>(ap);
            float4 v4 = *reinterpret_cast<const float4*>(vp);
            float4 m4 = *reinterpret_cast<const float4*>(colMean + n0 + bCol);
            float4 r4 = *reinterpret_cast<const float4*>(colRstd + n0 + bCol);
            float wc = lnW[kg], bc = lnB[kg];
            float4 o;
            o.x = v4.x * ((a4.x - m4.x) * r4.x * wc + bc);
            o.y = v4.y * ((a4.y - m4.y) * r4.y * wc + bc);
            o.z = v4.z * ((a4.z - m4.z) * r4.z * wc + bc);
            o.w = v4.w * ((a4.w - m4.w) * r4.w * wc + bc);
            return o;
        } else {
            const float* bp = B + (((size_t)(bg * CB + kg)) << 16) + hw0 + bCol;
            return *reinterpret_cast<const float4*>(bp);
        }
    };

    float acc[8][8];
#pragma unroll
    for (int i = 0; i < 8; i++)
#pragma unroll
        for (int j = 0; j < 8; j++) acc[i][j] = 0.f;

    {
        float4 pa = loadA(0);
        float4 pb = loadB(0);
        As[0][aCol + 0][aRow] = pa.x;
        As[0][aCol + 1][aRow] = pa.y;
        As[0][aCol + 2][aRow] = pa.z;
        As[0][aCol + 3][aRow] = pa.w;
        *reinterpret_cast<float4*>(&Bs[0][bRow][bCol]) = pb;
    }
    __syncthreads();

    const int ntiles = K >> 3;
    int buf = 0;
    const int ty8 = (t >> 4) * 8;
    const int tx8 = (t & 15) * 8;

    for (int kt = 0; kt < ntiles; kt++) {
        float4 pa, pb;
        bool has = (kt + 1 < ntiles);
        if (has) { pa = loadA(kt + 1); pb = loadB(kt + 1); }

#pragma unroll
        for (int kk = 0; kk < 8; kk++) {
            float4 a0 = *reinterpret_cast<const float4*>(&As[buf][kk][ty8]);
            float4 a1 = *reinterpret_cast<const float4*>(&As[buf][kk][ty8 + 4]);
            float4 b0 = *reinterpret_cast<const float4*>(&Bs[buf][kk][tx8]);
            float4 b1 = *reinterpret_cast<const float4*>(&Bs[buf][kk][tx8 + 4]);
            float av[8] = {a0.x, a0.y, a0.z, a0.w, a1.x, a1.y, a1.z, a1.w};
            float bv[8] = {b0.x, b0.y, b0.z, b0.w, b1.x, b1.y, b1.z, b1.w};
#pragma unroll
            for (int i = 0; i < 8; i++)
#pragma unroll
                for (int j = 0; j < 8; j++)
                    acc[i][j] += av[i] * bv[j];
        }

        if (has) {
            int nbuf = buf ^ 1;
            As[nbuf][aCol + 0][aRow] = pa.x;
            As[nbuf][aCol + 1][aRow] = pa.y;
            As[nbuf][aCol + 2][aRow] = pa.z;
            As[nbuf][aCol + 3][aRow] = pa.w;
            *reinterpret_cast<float4*>(&Bs[nbuf][bRow][bCol]) = pb;
            __syncthreads();
            buf = nbuf;
        }
    }

    if (MODE == 1) {
        float cm[8], cr[8];
        *reinterpret_cast<float4*>(&cm[0]) = *reinterpret_cast<const float4*>(colMean + n0 + tx8);
        *reinterpret_cast<float4*>(&cm[4]) = *reinterpret_cast<const float4*>(colMean + n0 + tx8 + 4);
        *reinterpret_cast<float4*>(&cr[0]) = *reinterpret_cast<const float4*>(colRstd + n0 + tx8);
        *reinterpret_cast<float4*>(&cr[4]) = *reinterpret_cast<const float4*>(colRstd + n0 + tx8 + 4);
#pragma unroll
        for (int i = 0; i < 8; i++) {
            int o = m0 + ty8 + i;
            float sv = rowS[o], tv = rowT[o];
            float* cptr = Cc + (((size_t)(bg * CO + o)) << 16) + hw0 + tx8;
            float4 o0, o1;
            o0.x = cr[0] * (acc[i][0] - cm[0] * sv) + tv;
            o0.y = cr[1] * (acc[i][1] - cm[1] * sv) + tv;
            o0.z = cr[2] * (acc[i][2] - cm[2] * sv) + tv;
            o0.w = cr[3] * (acc[i][3] - cm[3] * sv) + tv;
            o1.x = cr[4] * (acc[i][4] - cm[4] * sv) + tv;
            o1.y = cr[5] * (acc[i][5] - cm[5] * sv) + tv;
            o1.z = cr[6] * (acc[i][6] - cm[6] * sv) + tv;
            o1.w = cr[7] * (acc[i][7] - cm[7] * sv) + tv;
            *reinterpret_cast<float4*>(cptr)     = o0;
            *reinterpret_cast<float4*>(cptr + 4) = o1;
        }
    } else {
#pragma unroll
        for (int i = 0; i < 8; i++) {
            int o = m0 + ty8 + i;
            float sc = scaleRow[o];
            size_t idx = (((size_t)(bg * CO + o)) << 16) + hw0 + tx8;
            float4 x0 = *reinterpret_cast<const float4*>(Xres + idx);
            float4 x1 = *reinterpret_cast<const float4*>(Xres + idx + 4);
            float4 o0, o1;
            o0.x = x0.x + acc[i][0] * sc;
            o0.y = x0.y + acc[i][1] * sc;
            o0.z = x0.z + acc[i][2] * sc;
            o0.w = x0.w + acc[i][3] * sc;
            o1.x = x1.x + acc[i][4] * sc;
            o1.y = x1.y + acc[i][5] * sc;
            o1.z = x1.z + acc[i][6] * sc;
            o1.w = x1.w + acc[i][7] * sc;
            *reinterpret_cast<float4*>(Cc + idx)     = o0;
            *reinterpret_cast<float4*>(Cc + idx + 4) = o1;
        }
    }
}

// ---------------------------------------------------------------------------
// depthwise 3x3, SAME zero pad. grid (W/32, H/8, B*C), block (32, 8)
// ---------------------------------------------------------------------------
__global__ void dwconv_kernel(const float* __restrict__ in, const float* __restrict__ w,
                              float* __restrict__ out, int C) {
    int z = blockIdx.z;
    int b = z / C, c = z - b * C;
    __shared__ float tile[10][34];
    int h0 = blockIdx.y * 8, w0 = blockIdx.x * 32;
    const float* base = in + ((size_t)(b * C + c) << 16);
    int tid = threadIdx.y * 32 + threadIdx.x;
    for (int idx = tid; idx < 340; idx += 256) {
        int r = idx / 34, cc = idx - r * 34;
        int gh = h0 - 1 + r, gw = w0 - 1 + cc;
        float v = 0.f;
        if (gh >= 0 && gh < 256 && gw >= 0 && gw < 256) v = base[gh * 256 + gw];
        tile[r][cc] = v;
    }
    __syncthreads();
    const float* wc = w + c * 9;
    int ty = threadIdx.y, tx = threadIdx.x;
    float s = wc[0] * tile[ty][tx]     + wc[1] * tile[ty][tx + 1]     + wc[2] * tile[ty][tx + 2]
            + wc[3] * tile[ty + 1][tx] + wc[4] * tile[ty + 1][tx + 1] + wc[5] * tile[ty + 1][tx + 2]
            + wc[6] * tile[ty + 2][tx] + wc[7] * tile[ty + 2][tx + 1] + wc[8] * tile[ty + 2][tx + 2];
    out[((size_t)(b * C + c) << 16) + (h0 + ty) * 256 + (w0 + tx)] = s;
}

// ---------------------------------------------------------------------------
// FFN: dw3x3 on h (256ch) then gate: g[c] = d[c] * d[c+128], c in [0,128)
// grid (8, 32, B*128), block (32,8)
// ---------------------------------------------------------------------------
__global__ void gate_kernel(const float* __restrict__ h, const float* __restrict__ wdw,
                            float* __restrict__ g) {
    int z = blockIdx.z;
    int b = z >> 7, c = z & 127;
    __shared__ float t1s[10][34];
    __shared__ float t2s[10][34];
    int h0 = blockIdx.y * 8, w0 = blockIdx.x * 32;
    const float* base1 = h + ((size_t)(b * 256 + c) << 16);
    const float* base2 = h + ((size_t)(b * 256 + c + 128) << 16);
    int tid = threadIdx.y * 32 + threadIdx.x;
    for (int idx = tid; idx < 340; idx += 256) {
        int r = idx / 34, cc = idx - r * 34;
        int gh = h0 - 1 + r, gw = w0 - 1 + cc;
        bool ok = (gh >= 0 && gh < 256 && gw >= 0 && gw < 256);
        t1s[r][cc] = ok ? base1[gh * 256 + gw] : 0.f;
        t2s[r][cc] = ok ? base2[gh * 256 + gw] : 0.f;
    }
    __syncthreads();
    const float* w1 = wdw + (size_t)c * 9;
    const float* w2 = wdw + (size_t)(c + 128) * 9;
    int ty = threadIdx.y, tx = threadIdx.x;
    float a1 = w1[0]*t1s[ty][tx]   + w1[1]*t1s[ty][tx+1]   + w1[2]*t1s[ty][tx+2]
             + w1[3]*t1s[ty+1][tx] + w1[4]*t1s[ty+1][tx+1] + w1[5]*t1s[ty+1][tx+2]
             + w1[6]*t1s[ty+2][tx] + w1[7]*t1s[ty+2][tx+1] + w1[8]*t1s[ty+2][tx+2];
    float a2 = w2[0]*t2s[ty][tx]   + w2[1]*t2s[ty][tx+1]   + w2[2]*t2s[ty][tx+2]
             + w2[3]*t2s[ty+1][tx] + w2[4]*t2s[ty+1][tx+1] + w2[5]*t2s[ty+1][tx+2]
             + w2[6]*t2s[ty+2][tx] + w2[7]*t2s[ty+2][tx+1] + w2[8]*t2s[ty+2][tx+2];
    g[((size_t)(b * 128 + c) << 16) + (h0 + ty) * 256 + (w0 + tx)] = a1 * a2;
}

// ---------------------------------------------------------------------------
// patch FFT attention == 8x8 circular convolution per (channel, patch).
// attn(i,j) = sum_{a,b} q(a,b) * k((i-a)&7, (j-b)&7)
// grid: (8 pw-groups of 4 patches, 32 ph, B*32 ch-groups of 8), block 256.
// Each thread computes one full output row (8 values): FMA-bound, not LDS-bound.
// ---------------------------------------------------------------------------
__global__ __launch_bounds__(256)
void attn_kernel(const float* __restrict__ qkv, float* __restrict__ attn) {
    int z = blockIdx.z;
    int b = z >> 5;
    int cg = (z & 31) * 8;
    int ph = blockIdx.y, pwg = blockIdx.x;
    __shared__ float sq[8][4][72];   // [ch][patch][i*8+j], 72-stride pad
    __shared__ float sk[8][4][72];

    int t = threadIdx.x;
    {
        int i = t >> 5, col = t & 31;
        int lp = col >> 3, j = col & 7;
        int off = (ph * 8 + i) * 256 + pwg * 32 + col;
#pragma unroll
        for (int cidx = 0; cidx < 8; cidx++) {
            int c = cg + cidx;
            sq[cidx][lp][i * 8 + j] = qkv[((size_t)(b * 768 + c)       << 16) + off];
            sk[cidx][lp][i * 8 + j] = qkv[((size_t)(b * 768 + 256 + c) << 16) + off];
        }
    }
    __syncthreads();

    int cp   = t >> 3;          // 0..31
    int cidx = cp >> 2;
    int lp   = cp & 3;
    int i    = t & 7;

    float acc[8];
#pragma unroll
    for (int j = 0; j < 8; j++) acc[j] = 0.f;

#pragma unroll
    for (int a = 0; a < 8; a++) {
        int ra = (i - a) & 7;
        float qr[8], kr[8];
        *reinterpret_cast<float4*>(&qr[0]) = *reinterpret_cast<const float4*>(&sq[cidx][lp][a * 8]);
        *reinterpret_cast<float4*>(&qr[4]) = *reinterpret_cast<const float4*>(&sq[cidx][lp][a * 8 + 4]);
        *reinterpret_cast<float4*>(&kr[0]) = *reinterpret_cast<const float4*>(&sk[cidx][lp][ra * 8]);
        *reinterpret_cast<float4*>(&kr[4]) = *reinterpret_cast<const float4*>(&sk[cidx][lp][ra * 8 + 4]);
#pragma unroll
        for (int bq = 0; bq < 8; bq++)
#pragma unroll
            for (int j = 0; j < 8; j++)
                acc[j] += qr[bq] * kr[(j - bq) & 7];
    }

    size_t obase = (((size_t)(b * 256 + cg + cidx)) << 16)
                 + (ph * 8 + i) * 256 + pwg * 32 + lp * 8;
    float4 o0, o1;
    o0.x = acc[0]; o0.y = acc[1]; o0.z = acc[2]; o0.w = acc[3];
    o1.x = acc[4]; o1.y = acc[5]; o1.z = acc[6]; o1.w = acc[7];
    *reinterpret_cast<float4*>(attn + obase)     = o0;
    *reinterpret_cast<float4*>(attn + obase + 4) = o1;
}

// ---------------------------------------------------------------------------
extern "C" void kernel_launch(void* const* d_in, const int* in_sizes, int n_in,
                              void* d_out, int out_size) {
    const float* x      = (const float*)d_in[0];
    const float* n1w    = (const float*)d_in[1];
    const float* n1b    = (const float*)d_in[2];
    const float* w_h1   = (const float*)d_in[3];
    const float* w_dw1  = (const float*)d_in[4];
    const float* n2w    = (const float*)d_in[5];
    const float* n2b    = (const float*)d_in[6];
    const float* w_p1   = (const float*)d_in[7];
    const float* n3w    = (const float*)d_in[8];
    const float* n3b    = (const float*)d_in[9];
    const float* w_h2   = (const float*)d_in[10];
    const float* b_h2   = (const float*)d_in[11];
    const float* w_dw2  = (const float*)d_in[12];
    const float* w_p2   = (const float*)d_in[13];
    const float* scale1 = (const float*)d_in[14];
    const float* scale2 = (const float*)d_in[15];
    float* out = (float*)d_out;

    float *bufA, *bufB, *misc;
    cudaGetSymbolAddress((void**)&bufA, g_bufA);
    cudaGetSymbolAddress((void**)&bufB, g_bufB);
    cudaGetSymbolAddress((void**)&misc, g_misc);

    float* m1  = misc + OFF_M1;
    float* r1  = misc + OFF_R1;
    float* m2  = misc + OFF_M2;
    float* r2  = misc + OFF_R2;
    float* m3  = misc + OFF_M3;
    float* r3  = misc + OFF_R3;
    float* W1p = misc + OFF_W1P;
    float* s1  = misc + OFF_S1;
    float* t1  = misc + OFF_T1;
    float* W2p = misc + OFF_W2P;
    float* s2  = misc + OFF_S2;
    float* t2  = misc + OFF_T2;

    // stats + weight folds
    stats_kernel<<<512, 256>>>(x, m1, r1, 128);
    fold_kernel<<<3, 256>>>(w_h1, n1w, n1b, nullptr, W1p, s1, t1, 768, 128);
    fold_kernel<<<1, 256>>>(w_h2, n3w, n3b, b_h2,   W2p, s2, t2, 256, 128);

    // K1: hidden = LN1-folded conv1x1 (128 -> 768)
    gemm_kernel<1><<<dim3(1024, 6), 256>>>(W1p, x, bufA, 768, 128, 128, 768,
                                           m1, r1, s1, t1,
                                           nullptr, nullptr, nullptr, nullptr, nullptr);
    // K2: depthwise 3x3 over 768 channels
    dwconv_kernel<<<dim3(8, 32, 1536), dim3(32, 8)>>>(bufA, w_dw1, bufB, 768);

    // K3a: patch circular conv  (q = ch 0..255, k = ch 256..511 of qkv)
    attn_kernel<<<dim3(8, 32, 64), 256>>>(bufB, bufA);
    stats_kernel<<<512, 256>>>(bufA, m2, r2, 256);

    // K3b: x1 = x + scale1 * ( w_p1 @ ( v * LN2(attn) ) )
    gemm_kernel<3><<<dim3(1024, 1), 256>>>(w_p1, bufA, bufA + OFF_X1, 128, 256, 256, 128,
                                           m2, r2, nullptr, nullptr,
                                           bufB, n2w, n2b, x, scale1);

    // FFN branch
    stats_kernel<<<512, 256>>>(bufA + OFF_X1, m3, r3, 128);
    gemm_kernel<1><<<dim3(1024, 2), 256>>>(W2p, bufA + OFF_X1, bufB, 256, 128, 128, 256,
                                           m3, r3, s2, t2,
                                           nullptr, nullptr, nullptr, nullptr, nullptr);
    gate_kernel<<<dim3(8, 32, 256), dim3(32, 8)>>>(bufB, w_dw2, bufB + OFF_G);
    gemm_kernel<2><<<dim3(1024, 1), 256>>>(w_p2, bufB + OFF_G, out, 128, 128, 128, 128,
                                           nullptr, nullptr, nullptr, nullptr,
                                           nullptr, nullptr, nullptr,
                                           bufA + OFF_X1, scale2);
}